// round 13
// baseline (speedup 1.0000x reference)
#include <cuda_runtime.h>

// Problem dims
#define NX   256
#define NV   256
#define NY   128
#define NU   128
#define BATCH 8192
#define N3   768            // 2*NX + NV
#define EPSF 1.1920928955078125e-07f

// ---------------- device scratch (no allocations allowed) ----------------
__device__ float g_G[N3 * N3];          // X^T X
__device__ float g_part[256];           // sumsq partials
__device__ float g_sumsq;
__device__ float g_E[NX * NX];          // E, overwritten by in-place LU (no pivoting)
__device__ float g_LUt[NX * NX];        // transposed LU factors (for coalesced trsm)
__device__ float g_RHSt[640 * NX];      // RHS^T  [col][row] : [F | B1imp | B2]
__device__ float g_Z[NX * 640];         // solution [row][col] = [A_e | B1_e | B2_e]
__device__ float g_W1[NX * 384];        // [C1_e | D12_e]
__device__ float g_D11T[NV * NV];       // D11_e transposed: D11T[j][i] = D11_e[i][j]
__device__ float g_bmat[BATCH * NV];    // b
__device__ float g_w[BATCH * NV];       // w
__device__ float g_Wout[384 * 640];     // [[A_e B1_e B2_e]; [C2 D21 D22]]

// ---------------- 1) sum(X^2), deterministic 2-pass ----------------
__global__ void k_sumsq1(const float* __restrict__ X) {
    __shared__ float sred[256];
    int t = threadIdx.x;
    int base = blockIdx.x * 2304;                  // 589824 / 256
    float s = 0.f;
    #pragma unroll
    for (int e = 0; e < 9; e++) {
        float v = X[base + t + 256 * e];
        s += v * v;
    }
    sred[t] = s; __syncthreads();
    for (int off = 128; off; off >>= 1) {
        if (t < off) sred[t] += sred[t + off];
        __syncthreads();
    }
    if (t == 0) g_part[blockIdx.x] = sred[0];
}
__global__ void k_sumsq2() {
    __shared__ float sred[256];
    int t = threadIdx.x;
    sred[t] = g_part[t]; __syncthreads();
    for (int off = 128; off; off >>= 1) {
        if (t < off) sred[t] += sred[t + off];
        __syncthreads();
    }
    if (t == 0) g_sumsq = sred[0];
}

// ---------------- 2) G = X^T X (768x768, K=768) ----------------
__global__ void k_syrk(const float* __restrict__ X) {
    __shared__ float sA[16][65];
    __shared__ float sB[16][65];
    int t = threadIdx.x;
    int i0 = blockIdx.y * 64, j0 = blockIdx.x * 64;
    int tx = t & 15, ty = t >> 4;
    float acc[4][4];
    #pragma unroll
    for (int u = 0; u < 4; u++)
        #pragma unroll
        for (int v = 0; v < 4; v++) acc[u][v] = 0.f;

    for (int k0 = 0; k0 < N3; k0 += 16) {
        #pragma unroll
        for (int e = 0; e < 4; e++) {
            int idx = t + 256 * e;
            int kk = idx >> 6, c = idx & 63;
            sA[kk][c] = X[(k0 + kk) * N3 + i0 + c];
            sB[kk][c] = X[(k0 + kk) * N3 + j0 + c];
        }
        __syncthreads();
        #pragma unroll
        for (int kk = 0; kk < 16; kk++) {
            float a[4], b[4];
            #pragma unroll
            for (int u = 0; u < 4; u++) a[u] = sA[kk][ty + 16 * u];
            #pragma unroll
            for (int v = 0; v < 4; v++) b[v] = sB[kk][tx + 16 * v];
            #pragma unroll
            for (int u = 0; u < 4; u++)
                #pragma unroll
                for (int v = 0; v < 4; v++) acc[u][v] = fmaf(a[u], b[v], acc[u][v]);
        }
        __syncthreads();
    }
    #pragma unroll
    for (int u = 0; u < 4; u++)
        #pragma unroll
        for (int v = 0; v < 4; v++)
            g_G[(i0 + ty + 16 * u) * N3 + (j0 + tx + 16 * v)] = acc[u][v];
}

// ---------------- 3) assemble E, RHS^T, W1, D11^T ----------------
__global__ void k_assemble(const float* __restrict__ p,
                           const float* __restrict__ Y1,
                           const float* __restrict__ D12,
                           const float* __restrict__ B2) {
    int idx = blockIdx.x * 256 + threadIdx.x;
    float s = g_sumsq; if (s < EPSF) s = EPSF;
    float scale = p[0] * p[0] / s;

    if (idx < 65536) {
        // E[i][j] = (H11 + H33 + Y1 - Y1^T)/2
        int i = idx >> 8, j = idx & 255;
        float eps_d = (i == j) ? EPSF : 0.f;
        float h11 = scale * g_G[i * N3 + j] + eps_d;
        float h33 = scale * g_G[(512 + i) * N3 + 512 + j] + eps_d;
        g_E[idx] = 0.5f * (h11 + h33 + Y1[i * 256 + j] - Y1[j * 256 + i]);
    } else if (idx < 65536 + 163840) {
        // RHSt[c][i]: c<512 -> H[512+i][c] (= [F | B1imp]), else B2[i][c-512]
        int k = idx - 65536;
        int c = k >> 8, i = k & 255;
        float v;
        if (c < 512) v = scale * g_G[(512 + i) * N3 + c];
        else         v = B2[i * 128 + (c - 512)];
        g_RHSt[k] = v;
    } else if (idx < 65536 + 163840 + 98304) {
        // W1[i][j] = [C1_e | D12_e]
        int k = idx - (65536 + 163840);
        int i = k / 384, j = k - i * 384;
        float li = 2.0f / (scale * g_G[(256 + i) * N3 + 256 + i] + EPSF);
        float v;
        if (j < 256) v = -li * (scale * g_G[(256 + i) * N3 + j]);     // C1_e = -Lam^-1 H21
        else         v =  li * D12[i * 128 + (j - 256)];              // D12_e
        g_W1[k] = v;
    } else if (idx < 393216) {
        // D11T[j][i] = D11_e[i][j] = -Lam^-1[i] * H22[i][j], j<i
        int k = idx - (65536 + 163840 + 98304);
        int j = k >> 8, i = k & 255;
        float v = 0.f;
        if (i > j) {
            float li = 2.0f / (scale * g_G[(256 + i) * N3 + 256 + i] + EPSF);
            v = -li * (scale * g_G[(256 + i) * N3 + 256 + j]);
        }
        g_D11T[k] = v;
    }
}

// ---------------- 4) single-block LU, NO pivoting (sym(E) > 0 by construction)
__global__ void k_lu() {
    __shared__ float srow[256];
    int t = threadIdx.x;
    int lane = t & 31, w = t >> 5;       // 32 warps
    for (int k = 0; k < 256; k++) {
        __syncthreads();                  // prior trailing update visible
        if (t < 256) srow[t] = g_E[k * 256 + t];
        __syncthreads();
        float invd = 1.0f / srow[k];
        int jb = (k + 1) & ~31;
        for (int i = k + 1 + w; i < 256; i += 32) {
            float m = g_E[i * 256 + k] * invd;   // uniform address per warp
            if (lane == 0) g_E[i * 256 + k] = m;
            for (int j = jb + lane; j < 256; j += 32)
                if (j > k) g_E[i * 256 + j] = fmaf(-m, srow[j], g_E[i * 256 + j]);
        }
    }
}

// ---------------- 5) transpose LU factors ----------------
__global__ void k_trans() {
    int idx = blockIdx.x * 256 + threadIdx.x;   // 65536 total
    int j = idx >> 8, i = idx & 255;
    g_LUt[idx] = g_E[i * 256 + j];
}

// ---------------- 6) trsm: 640 columns, one warp each, right-looking ----------------
__global__ void k_trsm() {
    int gw = (blockIdx.x * blockDim.x + threadIdx.x) >> 5;
    int lane = threadIdx.x & 31;
    if (gw >= 640) return;
    float y[8];
    #pragma unroll
    for (int r = 0; r < 8; r++) y[r] = g_RHSt[gw * 256 + r * 32 + lane];

    // forward: L (unit diag)
    for (int j = 0; j < 256; j++) {
        float yj = __shfl_sync(0xffffffffu, y[j >> 5], j & 31);
        const float* lrow = g_LUt + j * 256;
        #pragma unroll
        for (int r = 0; r < 8; r++) {
            if (r * 32 + 31 <= j) continue;          // compile-time-ish skip
            int i = r * 32 + lane;
            if (i > j) y[r] = fmaf(-lrow[i], yj, y[r]);
        }
    }
    // backward: U
    for (int j = 255; j >= 0; j--) {
        float ujj = g_LUt[j * 256 + j];
        float yj = __shfl_sync(0xffffffffu, y[j >> 5], j & 31) / ujj;
        if (lane == (j & 31)) y[j >> 5] = yj;
        const float* urow = g_LUt + j * 256;
        #pragma unroll
        for (int r = 0; r < 8; r++) {
            if (r * 32 > j) continue;
            int i = r * 32 + lane;
            if (i < j) y[r] = fmaf(-urow[i], yj, y[r]);
        }
    }
    #pragma unroll
    for (int r = 0; r < 8; r++) g_Z[(r * 32 + lane) * 640 + gw] = y[r];
}

// ---------------- 7) build Wout ----------------
__global__ void k_wout(const float* __restrict__ C2, const float* __restrict__ D21,
                       const float* __restrict__ D22) {
    int idx = blockIdx.x * 256 + threadIdx.x;    // 245760 total
    int m = idx / 640, c = idx - m * 640;
    float v;
    if (m < 256) v = g_Z[idx];
    else {
        int mm = m - 256;
        if (c < 256)      v = C2 [mm * 256 + c];
        else if (c < 512) v = D21[mm * 256 + (c - 256)];
        else              v = D22[mm * 128 + (c - 512)];
    }
    g_Wout[idx] = v;
}

// ---------------- shared tiled fp32 GEMM body (concat-K A, split-N epilogue) ------
__device__ __forceinline__ void gemm_body(
    const float* __restrict__ A0, int w0,
    const float* __restrict__ A1, int w1,
    const float* __restrict__ A2, int w2,
    const float* __restrict__ W, int K,
    const float* __restrict__ bias0, const float* __restrict__ bias1, int nsplit,
    float* __restrict__ out0, int ld0, float* __restrict__ out1, int ld1)
{
    __shared__ float sA[16][65];
    __shared__ float sB[16][65];
    int t = threadIdx.x;
    int m0 = blockIdx.y * 64, n0 = blockIdx.x * 64;
    int tx = t & 15, ty = t >> 4;
    float acc[4][4];
    #pragma unroll
    for (int u = 0; u < 4; u++)
        #pragma unroll
        for (int v = 0; v < 4; v++) acc[u][v] = 0.f;

    for (int k0 = 0; k0 < K; k0 += 16) {
        const float* Ap; int wA, koff;
        if (k0 < w0)           { Ap = A0; wA = w0; koff = 0; }
        else if (k0 < w0 + w1) { Ap = A1; wA = w1; koff = w0; }
        else                   { Ap = A2; wA = w2; koff = w0 + w1; }
        #pragma unroll
        for (int e = 0; e < 4; e++) {
            int idx = t + 256 * e;
            int r = idx >> 4, kk = idx & 15;
            sA[kk][r] = Ap[(m0 + r) * wA + (k0 - koff) + kk];
            sB[kk][r] = W [(n0 + r) * K  + k0 + kk];
        }
        __syncthreads();
        #pragma unroll
        for (int kk = 0; kk < 16; kk++) {
            float a[4], b[4];
            #pragma unroll
            for (int u = 0; u < 4; u++) a[u] = sA[kk][ty + 16 * u];
            #pragma unroll
            for (int v = 0; v < 4; v++) b[v] = sB[kk][tx + 16 * v];
            #pragma unroll
            for (int u = 0; u < 4; u++)
                #pragma unroll
                for (int v = 0; v < 4; v++) acc[u][v] = fmaf(a[u], b[v], acc[u][v]);
        }
        __syncthreads();
    }
    #pragma unroll
    for (int u = 0; u < 4; u++) {
        int m = m0 + ty + 16 * u;
        #pragma unroll
        for (int v = 0; v < 4; v++) {
            int n = n0 + tx + 16 * v;
            float val = acc[u][v];
            if (n < nsplit) out0[m * ld0 + n] = val + bias0[n];
            else            out1[m * ld1 + (n - nsplit)] = val + bias1[n - nsplit];
        }
    }
}

// ---------------- 8) b = [state|inputs] @ W1^T + bv ----------------
__global__ void k_gemm_b(const float* __restrict__ state,
                         const float* __restrict__ inputs,
                         const float* __restrict__ bv) {
    gemm_body(state, 256, inputs, 128, inputs, 0,
              g_W1, 384, bv, bv, 256,
              g_bmat, 256, g_bmat, 256);
}

// ---------------- 9) equilibrium scan (right-looking, reduction-free) ----------------
__global__ void k_eq() {
    __shared__ float acc[32][257];
    __shared__ float wcol[32];
    int t = threadIdx.x;                   // 256 threads
    int row0 = blockIdx.x * 32;            // 256 blocks
    for (int idx = t; idx < 32 * 256; idx += 256)
        acc[idx >> 8][idx & 255] = 0.f;
    __syncthreads();

    int lane = t & 31, wrp = t >> 5;       // 8 warps, 4 rows each
    for (int j = 0; j < 256; j++) {
        if (t < 32) {
            float v = acc[t][j] + g_bmat[(row0 + t) * 256 + j];
            v = fmaxf(v, 0.f);
            wcol[t] = v;
            g_w[(row0 + t) * 256 + j] = v;
        }
        __syncthreads();
        const float* drow = g_D11T + j * 256;
        int jb = (j + 1) & ~31;
        #pragma unroll
        for (int rr = 0; rr < 4; rr++) {
            int r = wrp * 4 + rr;
            float wv = wcol[r];
            for (int i = jb + lane; i < 256; i += 32)
                if (i > j) acc[r][i] = fmaf(drow[i], wv, acc[r][i]);
        }
        __syncthreads();
    }
}

// ---------------- 10) out = [state|w|inputs] @ Wout^T + bias, split into x1/y ------
__global__ void k_gemm_out(const float* __restrict__ state,
                           const float* __restrict__ inputs,
                           const float* __restrict__ bx,
                           const float* __restrict__ by,
                           float* __restrict__ out) {
    gemm_body(state, 256, g_w, 256, inputs, 128,
              g_Wout, 640, bx, by, 256,
              out, 256, out + BATCH * NX, 128);
}

// ---------------- launcher ----------------
extern "C" void kernel_launch(void* const* d_in, const int* in_sizes, int n_in,
                              void* d_out, int out_size) {
    (void)in_sizes; (void)n_in; (void)out_size;
    const float* state  = (const float*)d_in[0];
    const float* inputs = (const float*)d_in[1];
    const float* X      = (const float*)d_in[2];
    const float* p      = (const float*)d_in[3];
    const float* B2     = (const float*)d_in[4];
    const float* D12    = (const float*)d_in[5];
    const float* Y1     = (const float*)d_in[6];
    const float* C2     = (const float*)d_in[7];
    const float* D21    = (const float*)d_in[8];
    const float* D22    = (const float*)d_in[9];
    const float* bx     = (const float*)d_in[10];
    const float* bv     = (const float*)d_in[11];
    const float* by     = (const float*)d_in[12];
    float* out = (float*)d_out;

    k_sumsq1<<<256, 256>>>(X);
    k_sumsq2<<<1, 256>>>();
    k_syrk<<<dim3(12, 12), 256>>>(X);
    k_assemble<<<1536, 256>>>(p, Y1, D12, B2);
    k_lu<<<1, 1024>>>();
    k_trans<<<256, 256>>>();
    k_trsm<<<160, 128>>>();
    k_wout<<<960, 256>>>(C2, D21, D22);
    k_gemm_b<<<dim3(4, 128), 256>>>(state, inputs, bv);
    k_eq<<<256, 256>>>();
    k_gemm_out<<<dim3(6, 128), 256>>>(state, inputs, bx, by, out);
}

// round 15
// speedup vs baseline: 2.5394x; 2.5394x over previous
#include <cuda_runtime.h>

// Problem dims
#define NX   256
#define NV   256
#define NY   128
#define NU   128
#define BATCH 8192
#define N3   768            // 2*NX + NV
#define EPSF 1.1920928955078125e-07f
#define NB   32

typedef unsigned long long ull;

// ---------------- f32x2 packed-FMA helpers (sm_103a FFMA2 path) ----------------
__device__ __forceinline__ ull pk2(float lo, float hi) {
    ull r; asm("mov.b64 %0, {%1,%2};" : "=l"(r) : "f"(lo), "f"(hi)); return r;
}
__device__ __forceinline__ void fma2(ull& d, ull a, ull b) {
    asm("fma.rn.f32x2 %0, %1, %2, %0;" : "+l"(d) : "l"(a), "l"(b));
}
__device__ __forceinline__ float2 up2(ull v) {
    float2 r; asm("mov.b64 {%0,%1}, %2;" : "=f"(r.x), "=f"(r.y) : "l"(v)); return r;
}

// ---------------- device scratch (no allocations allowed) ----------------
__device__ __align__(16) float g_G[N3 * N3];          // X^T X
__device__ __align__(16) float g_part[256];
__device__ float g_sumsq;
__device__ __align__(16) float g_E[NX * NX];          // E -> in-place LU (no pivoting)
__device__ __align__(16) float g_LUt[NX * NX];        // transposed LU factors
__device__ __align__(16) float g_RHSt[640 * NX];      // RHS^T [col][row]: [F | B1imp | B2]
__device__ __align__(16) float g_Z[NX * 640];         // solutions [row][col]
__device__ __align__(16) float g_W1[NX * 384];        // [C1_e | D12_e]
__device__ __align__(16) float g_D11T[NV * NV];       // D11T[j][i] = D11_e[i][j] (0 for i<=j)
__device__ __align__(16) float g_bmat[BATCH * NV];
__device__ __align__(16) float g_w[BATCH * NV];
__device__ __align__(16) float g_Wout[384 * 640];

// ---------------- 1) sum(X^2), deterministic 2-pass ----------------
__global__ void k_sumsq1(const float* __restrict__ X) {
    __shared__ float sred[256];
    int t = threadIdx.x;
    int base = blockIdx.x * 2304;
    float s = 0.f;
    #pragma unroll
    for (int e = 0; e < 9; e++) { float v = X[base + t + 256 * e]; s += v * v; }
    sred[t] = s; __syncthreads();
    for (int off = 128; off; off >>= 1) { if (t < off) sred[t] += sred[t + off]; __syncthreads(); }
    if (t == 0) g_part[blockIdx.x] = sred[0];
}
__global__ void k_sumsq2() {
    __shared__ float sred[256];
    int t = threadIdx.x;
    sred[t] = g_part[t]; __syncthreads();
    for (int off = 128; off; off >>= 1) { if (t < off) sred[t] += sred[t + off]; __syncthreads(); }
    if (t == 0) g_sumsq = sred[0];
}

// ---------------- 2) G = X^T X (768x768, K=768), f32x2 inner ----------------
__global__ void __launch_bounds__(256) k_syrk(const float* __restrict__ X) {
    __shared__ float sA[16 * 64];
    __shared__ float sB[16 * 64];
    int t = threadIdx.x;
    int i0 = blockIdx.y * 64, j0 = blockIdx.x * 64;
    int tx = t & 15, ty = t >> 4;
    ull acc[4][2] = {};

    int kk = t >> 4, q = t & 15;       // loader mapping: kk 0..15, col 4q..4q+3
    for (int k0 = 0; k0 < N3; k0 += 16) {
        *(float4*)&sA[kk * 64 + 4 * q] = *(const float4*)&X[(k0 + kk) * N3 + i0 + 4 * q];
        *(float4*)&sB[kk * 64 + 4 * q] = *(const float4*)&X[(k0 + kk) * N3 + j0 + 4 * q];
        __syncthreads();
        #pragma unroll
        for (int k = 0; k < 16; k++) {
            float4 a4 = *(float4*)&sA[k * 64 + ty * 4];
            float4 b4 = *(float4*)&sB[k * 64 + tx * 4];
            ull b01 = pk2(b4.x, b4.y), b23 = pk2(b4.z, b4.w);
            float av[4] = {a4.x, a4.y, a4.z, a4.w};
            #pragma unroll
            for (int u = 0; u < 4; u++) {
                ull au = pk2(av[u], av[u]);
                fma2(acc[u][0], au, b01);
                fma2(acc[u][1], au, b23);
            }
        }
        __syncthreads();
    }
    #pragma unroll
    for (int u = 0; u < 4; u++) {
        float2 lo = up2(acc[u][0]), hi = up2(acc[u][1]);
        float4 o = make_float4(lo.x, lo.y, hi.x, hi.y);
        *(float4*)&g_G[(i0 + ty * 4 + u) * N3 + j0 + tx * 4] = o;
    }
}

// ---------------- 3) assemble E, RHS^T, W1, D11^T ----------------
__global__ void k_assemble(const float* __restrict__ p,
                           const float* __restrict__ Y1,
                           const float* __restrict__ D12,
                           const float* __restrict__ B2) {
    int idx = blockIdx.x * 256 + threadIdx.x;
    float s = g_sumsq; if (s < EPSF) s = EPSF;
    float scale = p[0] * p[0] / s;

    if (idx < 65536) {
        int i = idx >> 8, j = idx & 255;
        float eps_d = (i == j) ? EPSF : 0.f;
        float h11 = scale * g_G[i * N3 + j] + eps_d;
        float h33 = scale * g_G[(512 + i) * N3 + 512 + j] + eps_d;
        g_E[idx] = 0.5f * (h11 + h33 + Y1[i * 256 + j] - Y1[j * 256 + i]);
    } else if (idx < 65536 + 163840) {
        int k = idx - 65536;
        int c = k >> 8, i = k & 255;
        float v;
        if (c < 512) v = scale * g_G[(512 + i) * N3 + c];
        else         v = B2[i * 128 + (c - 512)];
        g_RHSt[k] = v;
    } else if (idx < 65536 + 163840 + 98304) {
        int k = idx - (65536 + 163840);
        int i = k / 384, j = k - i * 384;
        float li = 2.0f / (scale * g_G[(256 + i) * N3 + 256 + i] + EPSF);
        float v;
        if (j < 256) v = -li * (scale * g_G[(256 + i) * N3 + j]);
        else         v =  li * D12[i * 128 + (j - 256)];
        g_W1[k] = v;
    } else if (idx < 393216) {
        int k = idx - (65536 + 163840 + 98304);
        int j = k >> 8, i = k & 255;
        float v = 0.f;
        if (i > j) {
            float li = 2.0f / (scale * g_G[(256 + i) * N3 + 256 + i] + EPSF);
            v = -li * (scale * g_G[(256 + i) * N3 + 256 + j]);
        }
        g_D11T[k] = v;
    }
}

// ---------------- 4a) blocked LU: panel factor (NB=32 cols, in shared) ----------
__global__ void k_panel(int pc) {
    __shared__ float sp[256 * NB];          // 32 KB
    int rem = 256 - pc;
    int t = threadIdx.x;                     // 512 threads
    for (int i = t; i < rem * 8; i += 512) {
        int r = i >> 3, q = i & 7;
        *(float4*)&sp[r * 32 + 4 * q] = *(const float4*)&g_E[(pc + r) * 256 + pc + 4 * q];
    }
    __syncthreads();
    int lane = t & 31, w = t >> 5;           // 16 warps
    for (int j = 0; j < NB; j++) {
        float inv = 1.0f / sp[j * 32 + j];
        float pivc = sp[j * 32 + lane];
        for (int r = j + 1 + w; r < rem; r += 16) {
            float m = sp[r * 32 + j] * inv;
            if (lane == 0) sp[r * 32 + j] = m;
            if (lane > j)  sp[r * 32 + lane] = fmaf(-m, pivc, sp[r * 32 + lane]);
        }
        __syncthreads();
    }
    for (int i = t; i < rem * 8; i += 512) {
        int r = i >> 3, q = i & 7;
        *(float4*)&g_E[(pc + r) * 256 + pc + 4 * q] = *(float4*)&sp[r * 32 + 4 * q];
    }
}

// ---------------- 4b) blocked LU: U12 = L11^{-1} A12 ----------------
__global__ void k_utrsm(int pc) {
    __shared__ float LshT[32 * 33];          // transposed L11
    int t = threadIdx.x;                      // 256
    for (int i = t; i < 1024; i += 256) {
        int r = i >> 5, c = i & 31;
        LshT[c * 33 + r] = g_E[(pc + r) * 256 + pc + c];
    }
    __syncthreads();
    int lane = t & 31, w = t >> 5;
    int col = pc + 32 + blockIdx.x * 8 + w;
    float v = g_E[(pc + lane) * 256 + col];
    #pragma unroll
    for (int j = 0; j < 32; j++) {
        float xj = __shfl_sync(0xffffffffu, v, j);
        if (lane > j) v = fmaf(-LshT[j * 33 + lane], xj, v);
    }
    g_E[(pc + lane) * 256 + col] = v;
}

// ---------------- 4c) blocked LU: Schur update A22 -= L21 @ U12 ----------------
__global__ void k_schur(int pc) {
    __shared__ float sA[32 * 32];            // sA[kk][m] (L21 transposed to k-major)
    __shared__ float sB[32 * 32];            // sB[kk][n]
    int t = threadIdx.x;                      // 256
    int base = pc + 32;
    int i0 = base + blockIdx.y * 32, j0 = base + blockIdx.x * 32;
    {
        int r = t >> 3, q = t & 7;
        float4 a = *(const float4*)&g_E[(i0 + r) * 256 + pc + 4 * q];
        sA[(4 * q + 0) * 32 + r] = a.x;
        sA[(4 * q + 1) * 32 + r] = a.y;
        sA[(4 * q + 2) * 32 + r] = a.z;
        sA[(4 * q + 3) * 32 + r] = a.w;
        *(float4*)&sB[r * 32 + 4 * q] = *(const float4*)&g_E[(pc + r) * 256 + j0 + 4 * q];
    }
    __syncthreads();
    int tx = t & 7, ty = t >> 3;
    ull acc[2] = {0, 0};
    #pragma unroll
    for (int kk = 0; kk < 32; kk++) {
        float a = sA[kk * 32 + ty];
        float4 b4 = *(float4*)&sB[kk * 32 + tx * 4];
        ull au = pk2(a, a);
        fma2(acc[0], au, pk2(b4.x, b4.y));
        fma2(acc[1], au, pk2(b4.z, b4.w));
    }
    float2 c01 = up2(acc[0]), c23 = up2(acc[1]);
    float4* cp = (float4*)&g_E[(i0 + ty) * 256 + j0 + tx * 4];
    float4 c = *cp;
    c.x -= c01.x; c.y -= c01.y; c.z -= c23.x; c.w -= c23.y;
    *cp = c;
}

// ---------------- 5) transpose LU factors ----------------
__global__ void k_trans() {
    int idx = blockIdx.x * 256 + threadIdx.x;
    int j = idx >> 8, i = idx & 255;
    g_LUt[idx] = g_E[i * 256 + j];
}

// ---------------- 6) trsm: 640 columns, one warp each ----------------
__global__ void k_trsm() {
    int gw = (blockIdx.x * blockDim.x + threadIdx.x) >> 5;
    int lane = threadIdx.x & 31;
    if (gw >= 640) return;
    float y[8];
    #pragma unroll
    for (int r = 0; r < 8; r++) y[r] = g_RHSt[gw * 256 + r * 32 + lane];

    for (int j = 0; j < 256; j++) {
        float yj = __shfl_sync(0xffffffffu, y[j >> 5], j & 31);
        const float* lrow = g_LUt + j * 256;
        #pragma unroll
        for (int r = 0; r < 8; r++) {
            int i = r * 32 + lane;
            if (i > j) y[r] = fmaf(-lrow[i], yj, y[r]);
        }
    }
    for (int j = 255; j >= 0; j--) {
        float ujj = g_LUt[j * 256 + j];
        float yj = __shfl_sync(0xffffffffu, y[j >> 5], j & 31) / ujj;
        if (lane == (j & 31)) y[j >> 5] = yj;
        const float* urow = g_LUt + j * 256;
        #pragma unroll
        for (int r = 0; r < 8; r++) {
            int i = r * 32 + lane;
            if (i < j) y[r] = fmaf(-urow[i], yj, y[r]);
        }
    }
    #pragma unroll
    for (int r = 0; r < 8; r++) g_Z[(r * 32 + lane) * 640 + gw] = y[r];
}

// ---------------- 7) build Wout ----------------
__global__ void k_wout(const float* __restrict__ C2, const float* __restrict__ D21,
                       const float* __restrict__ D22) {
    int idx = blockIdx.x * 256 + threadIdx.x;    // 245760 total
    int m = idx / 640, c = idx - m * 640;
    float v;
    if (m < 256) v = g_Z[idx];
    else {
        int mm = m - 256;
        if (c < 256)      v = C2 [mm * 256 + c];
        else if (c < 512) v = D21[mm * 256 + (c - 256)];
        else              v = D22[mm * 128 + (c - 512)];
    }
    g_Wout[idx] = v;
}

// ---------------- tiled fp32 GEMM body, f32x2 FMA, concat-K A, split-N out ------
__device__ __forceinline__ void gemm_body(
    const float* __restrict__ A0, int w0,
    const float* __restrict__ A1, int w1,
    const float* __restrict__ A2, int w2,
    const float* __restrict__ W, int K,
    const float* __restrict__ bias0, const float* __restrict__ bias1, int nsplit,
    float* __restrict__ out0, int ld0, float* __restrict__ out1, int ld1)
{
    __shared__ float sA[16 * 64];
    __shared__ float sB[16 * 64];
    int t = threadIdx.x;
    int m0 = blockIdx.y * 64, n0 = blockIdx.x * 64;
    int tx = t & 15, ty = t >> 4;
    ull acc[4][2] = {};

    int lr = t >> 2, lq = t & 3;         // loader: row 0..63, k-quad 0..3

    for (int k0 = 0; k0 < K; k0 += 16) {
        const float* Ap; int wA, koff;
        if (k0 < w0)           { Ap = A0; wA = w0; koff = 0; }
        else if (k0 < w0 + w1) { Ap = A1; wA = w1; koff = w0; }
        else                   { Ap = A2; wA = w2; koff = w0 + w1; }
        float4 av = *(const float4*)&Ap[(m0 + lr) * wA + (k0 - koff) + 4 * lq];
        float4 bv = *(const float4*)&W [(n0 + lr) * K  + k0 + 4 * lq];
        sA[(4 * lq + 0) * 64 + lr] = av.x;
        sA[(4 * lq + 1) * 64 + lr] = av.y;
        sA[(4 * lq + 2) * 64 + lr] = av.z;
        sA[(4 * lq + 3) * 64 + lr] = av.w;
        sB[(4 * lq + 0) * 64 + lr] = bv.x;
        sB[(4 * lq + 1) * 64 + lr] = bv.y;
        sB[(4 * lq + 2) * 64 + lr] = bv.z;
        sB[(4 * lq + 3) * 64 + lr] = bv.w;
        __syncthreads();
        #pragma unroll
        for (int kk = 0; kk < 16; kk++) {
            float4 a4 = *(float4*)&sA[kk * 64 + ty * 4];
            float4 b4 = *(float4*)&sB[kk * 64 + tx * 4];
            ull b01 = pk2(b4.x, b4.y), b23 = pk2(b4.z, b4.w);
            float avr[4] = {a4.x, a4.y, a4.z, a4.w};
            #pragma unroll
            for (int u = 0; u < 4; u++) {
                ull au = pk2(avr[u], avr[u]);
                fma2(acc[u][0], au, b01);
                fma2(acc[u][1], au, b23);
            }
        }
        __syncthreads();
    }
    int n = n0 + tx * 4;
    #pragma unroll
    for (int u = 0; u < 4; u++) {
        int m = m0 + ty * 4 + u;
        float2 lo = up2(acc[u][0]), hi = up2(acc[u][1]);
        if (n < nsplit) {
            float4 bs = *(const float4*)&bias0[n];
            float4 o = make_float4(lo.x + bs.x, lo.y + bs.y, hi.x + bs.z, hi.y + bs.w);
            *(float4*)&out0[m * ld0 + n] = o;
        } else {
            int nn = n - nsplit;
            float4 bs = *(const float4*)&bias1[nn];
            float4 o = make_float4(lo.x + bs.x, lo.y + bs.y, hi.x + bs.z, hi.y + bs.w);
            *(float4*)&out1[m * ld1 + nn] = o;
        }
    }
}

// ---------------- 8) b = [state|inputs] @ W1^T + bv ----------------
__global__ void __launch_bounds__(256) k_gemm_b(const float* __restrict__ state,
                         const float* __restrict__ inputs,
                         const float* __restrict__ bv) {
    gemm_body(state, 256, inputs, 128, inputs, 0,
              g_W1, 384, bv, bv, 256,
              g_bmat, 256, g_bmat, 256);
}

// ---------------- 9) equilibrium scan, all-register, no barriers ----------------
__global__ void __launch_bounds__(256) k_eq() {
    int t = threadIdx.x;
    int lane = t & 31, wp = t >> 5;
    int row0 = (blockIdx.x * 8 + wp) * 8;     // 8 warps/block, 8 rows/warp
    float acc[8][8];                           // [row][chunk]: col = chunk*32 + lane
    #pragma unroll
    for (int rr = 0; rr < 8; rr++)
        #pragma unroll
        for (int c = 0; c < 8; c++)
            acc[rr][c] = g_bmat[(row0 + rr) * 256 + c * 32 + lane];

    const float* dbase = g_D11T + lane;
    #pragma unroll
    for (int jc = 0; jc < 8; jc++) {
        for (int jj = 0; jj < 32; jj++) {
            int j = jc * 32 + jj;
            float wv[8];
            #pragma unroll
            for (int rr = 0; rr < 8; rr++) {
                float v = __shfl_sync(0xffffffffu, acc[rr][jc], jj);
                v = fmaxf(v, 0.f);
                wv[rr] = v;
                if (lane == jj) acc[rr][jc] = v;   // finalize w in place
            }
            const float* dr = dbase + j * 256;
            #pragma unroll
            for (int c = 0; c < 8; c++) {
                if (c < jc) continue;              // jc is unroll-constant
                float dv = dr[c * 32];
                if (c == jc && lane <= jj) dv = 0.f;  // protect finalized w slots
                #pragma unroll
                for (int rr = 0; rr < 8; rr++)
                    acc[rr][c] = fmaf(dv, wv[rr], acc[rr][c]);
            }
        }
    }
    #pragma unroll
    for (int rr = 0; rr < 8; rr++)
        #pragma unroll
        for (int c = 0; c < 8; c++)
            g_w[(row0 + rr) * 256 + c * 32 + lane] = acc[rr][c];
}

// ---------------- 10) out = [state|w|inputs] @ Wout^T + bias ----------------
__global__ void __launch_bounds__(256) k_gemm_out(const float* __restrict__ state,
                           const float* __restrict__ inputs,
                           const float* __restrict__ bx,
                           const float* __restrict__ by,
                           float* __restrict__ out) {
    gemm_body(state, 256, g_w, 256, inputs, 128,
              g_Wout, 640, bx, by, 256,
              out, 256, out + BATCH * NX, 128);
}

// ---------------- launcher ----------------
extern "C" void kernel_launch(void* const* d_in, const int* in_sizes, int n_in,
                              void* d_out, int out_size) {
    (void)in_sizes; (void)n_in; (void)out_size;
    const float* state  = (const float*)d_in[0];
    const float* inputs = (const float*)d_in[1];
    const float* X      = (const float*)d_in[2];
    const float* p      = (const float*)d_in[3];
    const float* B2     = (const float*)d_in[4];
    const float* D12    = (const float*)d_in[5];
    const float* Y1     = (const float*)d_in[6];
    const float* C2     = (const float*)d_in[7];
    const float* D21    = (const float*)d_in[8];
    const float* D22    = (const float*)d_in[9];
    const float* bx     = (const float*)d_in[10];
    const float* bv     = (const float*)d_in[11];
    const float* by     = (const float*)d_in[12];
    float* out = (float*)d_out;

    k_sumsq1<<<256, 256>>>(X);
    k_sumsq2<<<1, 256>>>();
    k_syrk<<<dim3(12, 12), 256>>>(X);
    k_assemble<<<1536, 256>>>(p, Y1, D12, B2);

    // blocked LU (no pivoting; sym(E) > 0 by construction)
    for (int pc = 0; pc < 256; pc += NB) {
        k_panel<<<1, 512>>>(pc);
        int rem2 = 256 - pc - NB;
        if (rem2 > 0) {
            k_utrsm<<<rem2 / 8, 256>>>(pc);
            k_schur<<<dim3(rem2 / 32, rem2 / 32), 256>>>(pc);
        }
    }

    k_trans<<<256, 256>>>();
    k_trsm<<<160, 128>>>();
    k_wout<<<960, 256>>>(C2, D21, D22);
    k_gemm_b<<<dim3(4, 128), 256>>>(state, inputs, bv);
    k_eq<<<128, 256>>>();
    k_gemm_out<<<dim3(6, 128), 256>>>(state, inputs, bx, by, out);
}